// round 6
// baseline (speedup 1.0000x reference)
#include <cuda_runtime.h>

// QConv2d: x (B,1,64,64) f32, weights (4,4,3) f32 -> out (B,12,31,31) f32
//
// Closed-form reduction of the quantum circuit (verified symbolically):
//   Per 4x4 patch p (row-major kh,kw), n2 = sum p^2:
//     zn = sum (-1)^(kh&1) * sc(kw) * p^2,  sc = (+,-,-,+)    -> z0 = zn/n2
//     cn = sum_kw p[0][kw]p[3][kw] + p[1][kw]p[2][kw]         -> x0 = 2cn/n2
//   (CNOT ring is XOR-linear; MSB pairing = i ^ 12; real amplitudes => y0=0.)
//   Only U3(weights[k][0]) survives the partial trace. Per channel c = 3k+j:
//     out = cA[c]*x0 + cB[c]*z0
//     ex: A = ct^2 cos(f+o) - st^2 cos(f-o),  B = sin(t) cos(f)
//     ey: A = ct^2 sin(f+o) - st^2 sin(f-o),  B = sin(t) sin(f)
//     ez: A = -sin(t) cos(o),                 B = cos(t)

#define IMG_H 64
#define IMG_W 64
#define IMG_PIX (IMG_H * IMG_W)              // 4096
#define WO 31
#define LPATCH 961                           // 31*31
#define NKERN 4
#define NCH (3 * NKERN)                      // 12
#define OUT_PER_IMG (NCH * LPATCH)           // 11532 floats = 46128 B
#define OUT_VEC (OUT_PER_IMG / 4)            // 2883 float4 (exact)

__global__ __launch_bounds__(256, 4)
void qconv2d_kernel(const float* __restrict__ x,
                    const float* __restrict__ wts,
                    float* __restrict__ out)
{
    __shared__ float  img[IMG_PIX];          // 16 KB
    __shared__ float2 xz[LPATCH];            // 7.7 KB  (x0, z0) interleaved
    __shared__ float  cA[NCH];
    __shared__ float  cB[NCH];

    const int b   = blockIdx.x;
    const int tid = threadIdx.x;

    // ---- stage image into smem (float4, fully coalesced) ----
    {
        const float4* src = reinterpret_cast<const float4*>(x + (size_t)b * IMG_PIX);
        float4* dst = reinterpret_cast<float4*>(img);
        #pragma unroll
        for (int i = 0; i < 4; ++i)
            dst[tid + i * 256] = src[tid + i * 256];
    }

    // ---- per-kernel Bloch-rotation coefficients (warp 0, lanes 0..3) ----
    if (tid < NKERN) {
        const float th = wts[tid * 12 + 0];
        const float ph = wts[tid * 12 + 1];
        const float om = wts[tid * 12 + 2];
        float st, ct;   sincosf(0.5f * th, &st, &ct);
        const float ct2 = ct * ct, st2 = st * st;
        const float sinth = 2.0f * ct * st;
        const float costh = ct2 - st2;
        float spo, cpo; sincosf(ph + om, &spo, &cpo);
        float smo, cmo; sincosf(ph - om, &smo, &cmo);
        float sp,  cp;  sincosf(ph, &sp, &cp);
        float so,  co;  sincosf(om, &so, &co);
        cA[3 * tid + 0] = ct2 * cpo - st2 * cmo;   // ex <- x0
        cB[3 * tid + 0] = sinth * cp;              // ex <- z0
        cA[3 * tid + 1] = ct2 * spo - st2 * smo;   // ey <- x0
        cB[3 * tid + 1] = sinth * sp;              // ey <- z0
        cA[3 * tid + 2] = -sinth * co;             // ez <- x0
        cB[3 * tid + 2] = costh;                   // ez <- z0
    }
    __syncthreads();

    // ---- per-patch reduction: (x0, z0) invariants into smem ----
    #pragma unroll
    for (int it = 0; it < 4; ++it) {
        const int p = tid + it * 256;
        if (p < LPATCH) {
            const int ho = p / WO;
            const int wo = p - ho * WO;
            const float* rp = img + (2 * ho) * IMG_W + 2 * wo;

            float v[4][4];
            #pragma unroll
            for (int r = 0; r < 4; ++r) {
                const float2 a = *reinterpret_cast<const float2*>(rp + r * IMG_W);
                const float2 c = *reinterpret_cast<const float2*>(rp + r * IMG_W + 2);
                v[r][0] = a.x; v[r][1] = a.y; v[r][2] = c.x; v[r][3] = c.y;
            }

            float n2 = 0.0f, zn = 0.0f, cn = 0.0f;
            #pragma unroll
            for (int r = 0; r < 4; ++r) {
                const float s = (r & 1) ? -1.0f : 1.0f;
                const float q0 = v[r][0] * v[r][0];
                const float q1 = v[r][1] * v[r][1];
                const float q2 = v[r][2] * v[r][2];
                const float q3 = v[r][3] * v[r][3];
                n2 += q0 + q1 + q2 + q3;
                zn += s * (q0 - q1 - q2 + q3);
            }
            #pragma unroll
            for (int kw = 0; kw < 4; ++kw)
                cn += v[0][kw] * v[3][kw] + v[1][kw] * v[2][kw];

            const float inv = 1.0f / n2;
            xz[p] = make_float2(2.0f * cn * inv, zn * inv);
        }
    }
    __syncthreads();

    // ---- epilogue: reconstruct 12 channels, STG.128, one div per float4 ----
    {
        float4* dst = reinterpret_cast<float4*>(out + (size_t)b * OUT_PER_IMG);
        #pragma unroll
        for (int i = 0; i < 12; ++i) {
            const int vi = tid + i * 256;
            if (vi < OUT_VEC) {                    // 2883
                const int base = vi * 4;
                int c = base / LPATCH;             // mul-shift
                int p = base - c * LPATCH;
                float r[4];
                #pragma unroll
                for (int e = 0; e < 4; ++e) {
                    const float2 v2 = xz[p];
                    r[e] = cA[c] * v2.x + cB[c] * v2.y;
                    if (++p == LPATCH) { p = 0; ++c; }   // at most once per vec
                }
                dst[vi] = make_float4(r[0], r[1], r[2], r[3]);
            }
        }
    }
}

extern "C" void kernel_launch(void* const* d_in, const int* in_sizes, int n_in,
                              void* d_out, int out_size)
{
    const float* x   = (const float*)d_in[0];   // (B,1,64,64)
    const float* wts = (const float*)d_in[1];   // (4,4,3)
    float* out = (float*)d_out;                  // (B,12,31,31)
    const int B = in_sizes[0] / IMG_PIX;         // batch from input size
    (void)n_in; (void)out_size;
    qconv2d_kernel<<<B, 256>>>(x, wts, out);
}

// round 7
// speedup vs baseline: 1.5343x; 1.5343x over previous
#include <cuda_runtime.h>

// QConv2d: x (B,1,64,64) f32, weights (4,4,3) f32 -> out (B,12,31,31) f32
//
// Closed-form reduction of the quantum circuit (verified; rel_err 1.8e-7):
//   Per 4x4 patch p (row-major kh,kw), n2 = sum p^2:
//     zn = sum (-1)^(kh&1) * sc(kw) * p^2,  sc = (+,-,-,+)    -> z0 = zn/n2
//     cn = sum_kw p[0][kw]p[3][kw] + p[1][kw]p[2][kw]         -> x0 = 2cn/n2
//   Only U3(weights[k][0]) survives the partial trace. Per channel c = 3k+j:
//     out = cA[c]*x0 + cB[c]*z0
//
// R6 ncu: L1 50.2%, DRAM 6.9%, occ 33% -> shared-pipe bound, not HBM.
// Fix: drop the xz smem round-trip + epilogue phase. Warp lanes own
// consecutive patches p, so out[c*961 + p] is consecutive across the warp:
// direct STG.32 from registers is fully coalesced. One sync, 16 KB smem.

#define IMG_H 64
#define IMG_W 64
#define IMG_PIX (IMG_H * IMG_W)              // 4096
#define WO 31
#define LPATCH 961                           // 31*31
#define NKERN 4
#define NCH (3 * NKERN)                      // 12
#define OUT_PER_IMG (NCH * LPATCH)           // 11532

__global__ __launch_bounds__(256, 4)
void qconv2d_kernel(const float* __restrict__ x,
                    const float* __restrict__ wts,
                    float* __restrict__ out)
{
    __shared__ float img[IMG_PIX];           // 16 KB
    __shared__ float cA[NCH];
    __shared__ float cB[NCH];

    const int b   = blockIdx.x;
    const int tid = threadIdx.x;

    // ---- stage image into smem (float4, fully coalesced) ----
    {
        const float4* src = reinterpret_cast<const float4*>(x + (size_t)b * IMG_PIX);
        float4* dst = reinterpret_cast<float4*>(img);
        #pragma unroll
        for (int i = 0; i < 4; ++i)
            dst[tid + i * 256] = src[tid + i * 256];
    }

    // ---- per-kernel Bloch-rotation coefficients (warp 0, lanes 0..3) ----
    if (tid < NKERN) {
        const float th = wts[tid * 12 + 0];
        const float ph = wts[tid * 12 + 1];
        const float om = wts[tid * 12 + 2];
        float st, ct;   sincosf(0.5f * th, &st, &ct);
        const float ct2 = ct * ct, st2 = st * st;
        const float sinth = 2.0f * ct * st;
        const float costh = ct2 - st2;
        float spo, cpo; sincosf(ph + om, &spo, &cpo);
        float smo, cmo; sincosf(ph - om, &smo, &cmo);
        float sp,  cp;  sincosf(ph, &sp, &cp);
        float so,  co;  sincosf(om, &so, &co);
        cA[3 * tid + 0] = ct2 * cpo - st2 * cmo;   // ex <- x0
        cB[3 * tid + 0] = sinth * cp;              // ex <- z0
        cA[3 * tid + 1] = ct2 * spo - st2 * smo;   // ey <- x0
        cB[3 * tid + 1] = sinth * sp;              // ey <- z0
        cA[3 * tid + 2] = -sinth * co;             // ez <- x0
        cB[3 * tid + 2] = costh;                   // ez <- z0
    }
    __syncthreads();

    float* ob = out + (size_t)b * OUT_PER_IMG;

    // ---- per-patch compute + direct coalesced STG.32 stores ----
    #pragma unroll
    for (int it = 0; it < 4; ++it) {
        const int p = tid + it * 256;
        if (p < LPATCH) {
            const int ho = p / WO;
            const int wo = p - ho * WO;
            const float* rp = img + (2 * ho) * IMG_W + 2 * wo;

            float v[4][4];
            #pragma unroll
            for (int r = 0; r < 4; ++r) {
                const float2 a = *reinterpret_cast<const float2*>(rp + r * IMG_W);
                const float2 c = *reinterpret_cast<const float2*>(rp + r * IMG_W + 2);
                v[r][0] = a.x; v[r][1] = a.y; v[r][2] = c.x; v[r][3] = c.y;
            }

            float n2 = 0.0f, zn = 0.0f, cn = 0.0f;
            #pragma unroll
            for (int r = 0; r < 4; ++r) {
                const float s = (r & 1) ? -1.0f : 1.0f;
                const float q0 = v[r][0] * v[r][0];
                const float q1 = v[r][1] * v[r][1];
                const float q2 = v[r][2] * v[r][2];
                const float q3 = v[r][3] * v[r][3];
                n2 += q0 + q1 + q2 + q3;
                zn += s * (q0 - q1 - q2 + q3);
            }
            #pragma unroll
            for (int kw = 0; kw < 4; ++kw)
                cn += v[0][kw] * v[3][kw] + v[1][kw] * v[2][kw];

            const float inv = 1.0f / n2;
            const float x0 = 2.0f * cn * inv;
            const float z0 = zn * inv;

            // 12 warp-coalesced scalar stores (lanes hold consecutive p)
            #pragma unroll
            for (int c = 0; c < NCH; ++c)
                ob[c * LPATCH + p] = cA[c] * x0 + cB[c] * z0;
        }
    }
}

extern "C" void kernel_launch(void* const* d_in, const int* in_sizes, int n_in,
                              void* d_out, int out_size)
{
    const float* x   = (const float*)d_in[0];   // (B,1,64,64)
    const float* wts = (const float*)d_in[1];   // (4,4,3)
    float* out = (float*)d_out;                  // (B,12,31,31)
    const int B = in_sizes[0] / IMG_PIX;         // batch from input size
    (void)n_in; (void)out_size;
    qconv2d_kernel<<<B, 256>>>(x, wts, out);
}